// round 8
// baseline (speedup 1.0000x reference)
#include <cuda_runtime.h>
#include <math.h>
#include <stdint.h>

#define HH 512
#define WW 512
#define HWSZ (HH * WW)
#define NTHREADS 512
#define NWARPS 16
#define CLUSTER 8
#define RPC 64              // rows per CTA (CLUSTER * RPC == HH)
#define TILE_BYTES (RPC * WW * 4)
#define EPSV 1e-8f

__device__ __forceinline__ uint32_t smem_u32(const void* p) {
    uint32_t a;
    asm("{ .reg .u64 t; cvta.to.shared.u64 t, %1; cvt.u32.u64 %0, t; }"
        : "=r"(a) : "l"(p));
    return a;
}

__device__ __forceinline__ float dsmem_ld(uint32_t local_addr, uint32_t rank) {
    uint32_t ra; float v;
    asm("mapa.shared::cluster.u32 %0, %1, %2;" : "=r"(ra) : "r"(local_addr), "r"(rank));
    asm volatile("ld.shared::cluster.f32 %0, [%1];" : "=f"(v) : "r"(ra));
    return v;
}

__device__ __forceinline__ void cluster_sync_all() {
    asm volatile("barrier.cluster.arrive.aligned;" ::: "memory");
    asm volatile("barrier.cluster.wait.aligned;" ::: "memory");
}

__global__ __launch_bounds__(NTHREADS) __cluster_dims__(CLUSTER, 1, 1)
void ircn_kernel(
    const float* __restrict__ in,
    const float* __restrict__ gRow_p, const float* __restrict__ bRow_p,
    const float* __restrict__ gCol_p, const float* __restrict__ bCol_p,
    const float* __restrict__ gIns_p, const float* __restrict__ bIns_p,
    float* __restrict__ out, int C)
{
    extern __shared__ __align__(16) float4 tile4[];   // RPC x 128 float4 = 128 KB

    __shared__ __align__(16) float colS[WW];    // this CTA's column partials (64 rows)
    __shared__ __align__(16) float colSS[WW];
    __shared__ __align__(16) float colM[WW];    // full-height column mean / inv
    __shared__ __align__(16) float colI[WW];
    __shared__ float rowM[RPC];
    __shared__ float rowI[RPC];
    __shared__ float warpRed[NWARPS * 2];
    __shared__ float planePart[2];              // this CTA's plane-sum partials
    __shared__ float insStat[2];                // final instance mean / inv

    const int rank = blockIdx.x;                // CTA rank within the plane's cluster
    const int plane = blockIdx.y;               // b*C + c
    const int c = plane % C;
    const int b = plane / C;
    const int r0 = rank * RPC;                  // first global row owned by this CTA
    const float* __restrict__ p = in + (size_t)plane * HWSZ;

    const int tid = threadIdx.x;
    const int lane = tid & 31;
    const int wid = tid >> 5;

    colS[tid] = 0.f;
    colSS[tid] = 0.f;
    __syncthreads();

    // ---------------- Phase A: single DRAM read -> smem tile + stats ----------------
    float cs[16], css[16];
#pragma unroll
    for (int i = 0; i < 16; i++) { cs[i] = 0.f; css[i] = 0.f; }
    float psum = 0.f, pss = 0.f;                // plane partials (lane-replicated)

    for (int r = wid; r < RPC; r += NWARPS) {
        const float4* rp = (const float4*)(p + (size_t)(r0 + r) * WW);
        float4 v[4];
#pragma unroll
        for (int k = 0; k < 4; k++) v[k] = __ldcg(&rp[k * 32 + lane]);
#pragma unroll
        for (int k = 0; k < 4; k++) tile4[r * 128 + k * 32 + lane] = v[k];

        float s = 0.f, ss = 0.f;
#pragma unroll
        for (int k = 0; k < 4; k++) {
            s += (v[k].x + v[k].y) + (v[k].z + v[k].w);
            ss += v[k].x * v[k].x + v[k].y * v[k].y + v[k].z * v[k].z + v[k].w * v[k].w;
            cs[k * 4 + 0] += v[k].x;  css[k * 4 + 0] += v[k].x * v[k].x;
            cs[k * 4 + 1] += v[k].y;  css[k * 4 + 1] += v[k].y * v[k].y;
            cs[k * 4 + 2] += v[k].z;  css[k * 4 + 2] += v[k].z * v[k].z;
            cs[k * 4 + 3] += v[k].w;  css[k * 4 + 3] += v[k].w * v[k].w;
        }
#pragma unroll
        for (int o = 16; o > 0; o >>= 1) {
            s += __shfl_xor_sync(0xffffffffu, s, o);
            ss += __shfl_xor_sync(0xffffffffu, ss, o);
        }
        // row r is entirely owned by this CTA -> finalize row stats now
        if (lane == 0) {
            float m = s * (1.f / WW);
            float v2 = fmaxf(ss * (1.f / WW) - m * m, 0.f);
            rowM[r] = m;
            rowI[r] = 1.f / (sqrtf(v2 + EPSV) + EPSV);
        }
        psum += s;   // replicated across lanes; harmless
        pss += ss;
    }

    // flush per-lane column partials
#pragma unroll
    for (int k = 0; k < 4; k++) {
        int cbase = (k * 32 + lane) * 4;
#pragma unroll
        for (int j = 0; j < 4; j++) {
            atomicAdd(&colS[cbase + j], cs[k * 4 + j]);
            atomicAdd(&colSS[cbase + j], css[k * 4 + j]);
        }
    }
    if (lane == 0) { warpRed[wid] = psum; warpRed[NWARPS + wid] = pss; }
    __syncthreads();

    if (tid == 0) {
        float s = 0.f, ss = 0.f;
        for (int i = 0; i < NWARPS; i++) { s += warpRed[i]; ss += warpRed[NWARPS + i]; }
        planePart[0] = s;
        planePart[1] = ss;
    }
    __syncthreads();

    // ---------------- Cross-CTA reduction over the 8-CTA cluster ----------------
    cluster_sync_all();   // all partials written cluster-wide

    {
        const uint32_t aS = smem_u32(colS) + tid * 4;
        const uint32_t aSS = smem_u32(colSS) + tid * 4;
        float s = 0.f, ss = 0.f;
#pragma unroll
        for (int rk = 0; rk < CLUSTER; rk++) {
            s += dsmem_ld(aS, rk);
            ss += dsmem_ld(aSS, rk);
        }
        float mc = s * (1.f / HH);
        float vc = fmaxf(ss * (1.f / HH) - mc * mc, 0.f);
        colM[tid] = mc;
        colI[tid] = 1.f / (sqrtf(vc + EPSV) + EPSV);
    }
    if (tid == 0) {
        const uint32_t aP = smem_u32(planePart);
        float s = 0.f, ss = 0.f;
#pragma unroll
        for (int rk = 0; rk < CLUSTER; rk++) {
            s += dsmem_ld(aP, rk);
            ss += dsmem_ld(aP + 4, rk);
        }
        float m = s * (1.f / HWSZ);
        float v = fmaxf(ss * (1.f / HWSZ) - m * m, 0.f);
        insStat[0] = m;
        insStat[1] = 1.f / (sqrtf(v + EPSV) + EPSV);
    }
    __syncthreads();
    cluster_sync_all();   // all DSMEM reads complete before any CTA may retire

    // ---------------- Phase B: normalize from smem tile, write 3 outputs ----------------
    const float gRow = gRow_p[c], bRow = bRow_p[c];
    const float gCol = gCol_p[c], bCol = bCol_p[c];
    const float gIns = gIns_p[c], bIns = bIns_p[c];
    const float insM = insStat[0], insI = insStat[1];

    const size_t outBase = (size_t)b * 3 * C * HWSZ;
    float* __restrict__ oI = out + outBase + (size_t)c * HWSZ;
    float* __restrict__ oR = out + outBase + (size_t)(C + c) * HWSZ;
    float* __restrict__ oC = out + outBase + (size_t)(2 * C + c) * HWSZ;

    const float4* colM4 = (const float4*)colM;
    const float4* colI4 = (const float4*)colI;

    for (int r = wid; r < RPC; r += NWARPS) {
        const int gr = r0 + r;
        float4* oIp = (float4*)(oI + (size_t)gr * WW);
        float4* oRp = (float4*)(oR + (size_t)gr * WW);
        float4* oCp = (float4*)(oC + (size_t)gr * WW);
        const float rm = rowM[r];
        const float ri = rowI[r];
#pragma unroll
        for (int k = 0; k < 4; k++) {
            const int idx = k * 32 + lane;
            float4 v = tile4[r * 128 + idx];
            float4 cm = colM4[idx];
            float4 ci = colI4[idx];
            float4 o;
            // instance norm
            o.x = gIns * (v.x - insM) * insI + bIns;
            o.y = gIns * (v.y - insM) * insI + bIns;
            o.z = gIns * (v.z - insM) * insI + bIns;
            o.w = gIns * (v.w - insM) * insI + bIns;
            __stcs(&oIp[idx], o);
            // row norm
            o.x = gRow * (v.x - rm) * ri + bRow;
            o.y = gRow * (v.y - rm) * ri + bRow;
            o.z = gRow * (v.z - rm) * ri + bRow;
            o.w = gRow * (v.w - rm) * ri + bRow;
            __stcs(&oRp[idx], o);
            // col norm
            o.x = gCol * (v.x - cm.x) * ci.x + bCol;
            o.y = gCol * (v.y - cm.y) * ci.y + bCol;
            o.z = gCol * (v.z - cm.z) * ci.z + bCol;
            o.w = gCol * (v.w - cm.w) * ci.w + bCol;
            __stcs(&oCp[idx], o);
        }
    }
}

extern "C" void kernel_launch(void* const* d_in, const int* in_sizes, int n_in,
                              void* d_out, int out_size) {
    const float* in = (const float*)d_in[0];
    const float* gRow = (const float*)d_in[1];
    const float* bRow = (const float*)d_in[2];
    const float* gCol = (const float*)d_in[3];
    const float* bCol = (const float*)d_in[4];
    const float* gIns = (const float*)d_in[5];
    const float* bIns = (const float*)d_in[6];
    float* out = (float*)d_out;

    const int C = in_sizes[1];                  // 128
    const int nPlanes = in_sizes[0] / HWSZ;     // B*C = 256

    cudaFuncSetAttribute(ircn_kernel,
                         cudaFuncAttributeMaxDynamicSharedMemorySize, TILE_BYTES);

    dim3 grid(CLUSTER, nPlanes, 1);
    ircn_kernel<<<grid, NTHREADS, TILE_BYTES>>>(
        in, gRow, bRow, gCol, bCol, gIns, bIns, out, C);
}

// round 10
// speedup vs baseline: 1.5221x; 1.5221x over previous
#include <cuda_runtime.h>
#include <math.h>

#define HH 512
#define WW 512
#define HWSZ (HH * WW)
#define NTHREADS 512
#define NWARPS 16
#define EPSV 1e-8f
#define STAGE_ROWS 48
#define STAGE_BYTES (STAGE_ROWS * WW * 4)   // 96 KB dynamic smem

__global__ __launch_bounds__(NTHREADS, 2) void ircn_kernel(
    const float* __restrict__ in,
    const float* __restrict__ gRow_p, const float* __restrict__ bRow_p,
    const float* __restrict__ gCol_p, const float* __restrict__ bCol_p,
    const float* __restrict__ gIns_p, const float* __restrict__ bIns_p,
    float* __restrict__ out, int C)
{
    extern __shared__ __align__(16) float4 stage4[];   // STAGE_ROWS x 128 float4

    __shared__ __align__(16) float rowS[HH];
    __shared__ __align__(16) float rowSS[HH];
    __shared__ __align__(16) float colS[WW];
    __shared__ __align__(16) float colSS[WW];
    __shared__ float warpRed[NWARPS * 2];
    __shared__ float sIns[2];  // mean, inv

    const int plane = blockIdx.x;      // b*C + c
    const int c = plane % C;
    const int b = plane / C;
    const float* __restrict__ p = in + (size_t)plane * HWSZ;

    const int tid = threadIdx.x;
    const int lane = tid & 31;
    const int wid = tid >> 5;

    // init column accumulators (tid < 512 == WW)
    colS[tid] = 0.f;
    colSS[tid] = 0.f;
    __syncthreads();

    // ---------------- Phase A: stats (forward stream); stage head rows in smem ----
    float cs[16], css[16];
#pragma unroll
    for (int i = 0; i < 16; i++) { cs[i] = 0.f; css[i] = 0.f; }

    for (int r = wid; r < HH; r += NWARPS) {
        const float4* rp = (const float4*)(p + (size_t)r * WW);
        float4 v[4];
#pragma unroll
        for (int k = 0; k < 4; k++) v[k] = __ldcg(&rp[k * 32 + lane]);

        if (r < STAGE_ROWS) {
#pragma unroll
            for (int k = 0; k < 4; k++) stage4[r * 128 + k * 32 + lane] = v[k];
        }

        float s = 0.f, ss = 0.f;
#pragma unroll
        for (int k = 0; k < 4; k++) {
            s += (v[k].x + v[k].y) + (v[k].z + v[k].w);
            ss += v[k].x * v[k].x + v[k].y * v[k].y + v[k].z * v[k].z + v[k].w * v[k].w;
            cs[k * 4 + 0] += v[k].x;  css[k * 4 + 0] += v[k].x * v[k].x;
            cs[k * 4 + 1] += v[k].y;  css[k * 4 + 1] += v[k].y * v[k].y;
            cs[k * 4 + 2] += v[k].z;  css[k * 4 + 2] += v[k].z * v[k].z;
            cs[k * 4 + 3] += v[k].w;  css[k * 4 + 3] += v[k].w * v[k].w;
        }
#pragma unroll
        for (int o = 16; o > 0; o >>= 1) {
            s += __shfl_xor_sync(0xffffffffu, s, o);
            ss += __shfl_xor_sync(0xffffffffu, ss, o);
        }
        if (lane == 0) { rowS[r] = s; rowSS[r] = ss; }
    }

    // flush per-lane column partials (16 fixed columns per lane)
#pragma unroll
    for (int k = 0; k < 4; k++) {
        int cbase = (k * 32 + lane) * 4;
#pragma unroll
        for (int j = 0; j < 4; j++) {
            atomicAdd(&colS[cbase + j], cs[k * 4 + j]);
            atomicAdd(&colSS[cbase + j], css[k * 4 + j]);
        }
    }
    __syncthreads();

    // plane (instance) reduction from row sums
    {
        float s = rowS[tid], ss = rowSS[tid];
#pragma unroll
        for (int o = 16; o > 0; o >>= 1) {
            s += __shfl_xor_sync(0xffffffffu, s, o);
            ss += __shfl_xor_sync(0xffffffffu, ss, o);
        }
        if (lane == 0) { warpRed[wid] = s; warpRed[NWARPS + wid] = ss; }
    }
    __syncthreads();
    if (tid == 0) {
        float s = 0.f, ss = 0.f;
        for (int i = 0; i < NWARPS; i++) { s += warpRed[i]; ss += warpRed[NWARPS + i]; }
        float m = s * (1.f / HWSZ);
        float v = fmaxf(ss * (1.f / HWSZ) - m * m, 0.f);
        sIns[0] = m;
        sIns[1] = 1.f / (sqrtf(v + EPSV) + EPSV);
    }

    // convert row/col raw sums -> mean & inv (thread t touches only index t; the
    // plane reduce above already consumed rowS[tid]/rowSS[tid])
    {
        float m = rowS[tid] * (1.f / WW);
        float v = fmaxf(rowSS[tid] * (1.f / WW) - m * m, 0.f);
        rowS[tid] = m;
        rowSS[tid] = 1.f / (sqrtf(v + EPSV) + EPSV);

        float mc = colS[tid] * (1.f / HH);
        float vc = fmaxf(colSS[tid] * (1.f / HH) - mc * mc, 0.f);
        colS[tid] = mc;
        colSS[tid] = 1.f / (sqrtf(vc + EPSV) + EPSV);
    }
    __syncthreads();

    // ---------------- Phase B: normalize & write (REVERSE stream) ----------------
    // Tail of the plane is the most-recently-cached in L2 after phase A, so read
    // back-to-front (LIFO order matches LRU retention). Head rows come from smem.
    const float gRow = gRow_p[c], bRow = bRow_p[c];
    const float gCol = gCol_p[c], bCol = bCol_p[c];
    const float gIns = gIns_p[c], bIns = bIns_p[c];
    const float insM = sIns[0], insI = sIns[1];

    const size_t outBase = (size_t)b * 3 * C * HWSZ;
    float* __restrict__ oI = out + outBase + (size_t)c * HWSZ;
    float* __restrict__ oR = out + outBase + (size_t)(C + c) * HWSZ;
    float* __restrict__ oC = out + outBase + (size_t)(2 * C + c) * HWSZ;

    const float4* colM4 = (const float4*)colS;
    const float4* colI4 = (const float4*)colSS;

    for (int r = (HH - 1) - wid; r >= 0; r -= NWARPS) {
        const float4* rp = (const float4*)(p + (size_t)r * WW);
        float4* oIp = (float4*)(oI + (size_t)r * WW);
        float4* oRp = (float4*)(oR + (size_t)r * WW);
        float4* oCp = (float4*)(oC + (size_t)r * WW);
        const float rm = rowS[r];
        const float ri = rowSS[r];
        const bool staged = (r < STAGE_ROWS);
#pragma unroll
        for (int k = 3; k >= 0; k--) {
            const int idx = k * 32 + lane;
            float4 v = staged ? stage4[r * 128 + idx] : __ldcs(&rp[idx]);
            float4 cm = colM4[idx];
            float4 ci = colI4[idx];
            float4 o;
            // instance norm
            o.x = gIns * (v.x - insM) * insI + bIns;
            o.y = gIns * (v.y - insM) * insI + bIns;
            o.z = gIns * (v.z - insM) * insI + bIns;
            o.w = gIns * (v.w - insM) * insI + bIns;
            __stcs(&oIp[idx], o);
            // row norm
            o.x = gRow * (v.x - rm) * ri + bRow;
            o.y = gRow * (v.y - rm) * ri + bRow;
            o.z = gRow * (v.z - rm) * ri + bRow;
            o.w = gRow * (v.w - rm) * ri + bRow;
            __stcs(&oRp[idx], o);
            // col norm
            o.x = gCol * (v.x - cm.x) * ci.x + bCol;
            o.y = gCol * (v.y - cm.y) * ci.y + bCol;
            o.z = gCol * (v.z - cm.z) * ci.z + bCol;
            o.w = gCol * (v.w - cm.w) * ci.w + bCol;
            __stcs(&oCp[idx], o);
        }
    }
}

extern "C" void kernel_launch(void* const* d_in, const int* in_sizes, int n_in,
                              void* d_out, int out_size) {
    const float* in = (const float*)d_in[0];
    const float* gRow = (const float*)d_in[1];
    const float* bRow = (const float*)d_in[2];
    const float* gCol = (const float*)d_in[3];
    const float* bCol = (const float*)d_in[4];
    const float* gIns = (const float*)d_in[5];
    const float* bIns = (const float*)d_in[6];
    float* out = (float*)d_out;

    const int C = in_sizes[1];                  // 128
    const int nPlanes = in_sizes[0] / HWSZ;     // B*C = 256

    cudaFuncSetAttribute(ircn_kernel,
                         cudaFuncAttributeMaxDynamicSharedMemorySize, STAGE_BYTES);

    ircn_kernel<<<nPlanes, NTHREADS, STAGE_BYTES>>>(
        in, gRow, bRow, gCol, bCol, gIns, bIns, out, C);
}